// round 10
// baseline (speedup 1.0000x reference)
#include <cuda_runtime.h>
#include <cuda_bf16.h>

#define NMAX 100000
#define EMAX 1600000
#define F 32
#define NG 64
#define NPB 256
#define SCANB 1024

// ---------------- scratch (static device globals; no allocs) ----------------
__device__ int2     d_epack[EMAX];     // CSR-ordered (src_row, nrm-as-int)
__device__ int      d_degr[NMAX];      // out-degree (segment_sum over row)
__device__ int      d_cnt[NMAX];       // in-count per col (CSR sizes)
__device__ int      d_ptr[NMAX + 1];   // CSR offsets
__device__ int      d_fill[NMAX];      // running fill pointers
__device__ int      d_bsum[128];
__device__ int      d_boff[128];
__device__ float    d_t1[NMAX * F];    // Tx1 = prop(x)
__device__ float    d_p2[NMAX * F];    // P2  = prop(Tx1)
__device__ unsigned d_pool[NG * F];    // segment-max, order-preserving uint encoding
__device__ float    d_h1[NG * 1024];
__device__ float    d_h2[NG * 512];

__device__ __forceinline__ unsigned fenc(float f) {
    unsigned b = __float_as_uint(f);
    return (b & 0x80000000u) ? ~b : (b | 0x80000000u);
}
__device__ __forceinline__ float fdec(unsigned u) {
    return __uint_as_float((u & 0x80000000u) ? (u & 0x7FFFFFFFu) : ~u);
}

// ---------------- kernels ----------------

__global__ void k_init(int n) {
    int i = blockIdx.x * blockDim.x + threadIdx.x;
    if (i < n) { d_degr[i] = 0; d_cnt[i] = 0; }
    if (i < NG * F) d_pool[i] = 0x007FFFFFu;  // fenc(-inf)
}

// edge_index is int32. Count row-degree and col-incount directly from ei.
__global__ void k_count(const int* __restrict__ ei, int E) {
    int e = blockIdx.x * blockDim.x + threadIdx.x;
    if (e >= E) return;
    atomicAdd(&d_degr[ei[e]], 1);        // REDG (result unused)
    atomicAdd(&d_cnt[ei[E + e]], 1);
}

// exclusive prefix scan of d_cnt -> d_ptr (3-phase)
__global__ void k_scan1(int n) {
    __shared__ int s[SCANB];
    int i = blockIdx.x * SCANB + threadIdx.x;
    int v = (i < n) ? d_cnt[i] : 0;
    s[threadIdx.x] = v;
    __syncthreads();
#pragma unroll
    for (int off = 1; off < SCANB; off <<= 1) {
        int t = (threadIdx.x >= off) ? s[threadIdx.x - off] : 0;
        __syncthreads();
        s[threadIdx.x] += t;
        __syncthreads();
    }
    if (i < n) d_ptr[i] = s[threadIdx.x] - v;  // exclusive
    if (threadIdx.x == SCANB - 1) d_bsum[blockIdx.x] = s[SCANB - 1];
}

// parallel exclusive scan of <=128 block sums (was a 7.5us serial loop)
__global__ void k_scan2(int nb) {
    __shared__ int s[128];
    int t = threadIdx.x;
    int v = (t < nb) ? d_bsum[t] : 0;
    s[t] = v;
    __syncthreads();
#pragma unroll
    for (int off = 1; off < 128; off <<= 1) {
        int u = (t >= off) ? s[t - off] : 0;
        __syncthreads();
        s[t] += u;
        __syncthreads();
    }
    if (t < nb) d_boff[t] = s[t] - v;   // exclusive
}

__global__ void k_scan3(int n, int E) {
    int i = blockIdx.x * SCANB + threadIdx.x;
    if (i < n) {
        int p = d_ptr[i] + d_boff[blockIdx.x];
        d_ptr[i] = p;
        d_fill[i] = p;
    }
    if (i == 0) d_ptr[n] = E;
}

// scatter edges into CSR slots, computing nrm on the fly (reads ei directly)
__global__ void k_scatter(const int* __restrict__ ei, int E) {
    int e = blockIdx.x * blockDim.x + threadIdx.x;
    if (e >= E) return;
    int r = ei[e];
    int c = ei[E + e];
    int dr = d_degr[r];
    int dc = d_degr[c];
    float fr = (dr > 0) ? rsqrtf((float)dr) : 0.f;
    float fc = (dc > 0) ? rsqrtf((float)dc) : 0.f;
    float nrm = -(fr * fc);
    int p = atomicAdd(&d_fill[c], 1);
    d_epack[p] = make_int2(r, __float_as_int(nrm));
}

// gather propagation: dst[c] = sum_{e in CSR[c]} nrm_e * src[row_e]; warp/node.
// unroll-8 with int4-packed edge records (2 edges per load) for high MLP.
__global__ void __launch_bounds__(256) k_gather(const float* __restrict__ src,
                                                float* __restrict__ dst, int n) {
    int w = (blockIdx.x * blockDim.x + threadIdx.x) >> 5;
    int lane = threadIdx.x & 31;
    if (w >= n) return;
    int p = d_ptr[w];
    int pe = d_ptr[w + 1];
    float acc = 0.f;

    // align to even index for int4 (16B) edge loads
    if ((p & 1) && p < pe) {
        int2 e = d_epack[p];
        acc = fmaf(__int_as_float(e.y), __ldg(&src[e.x * F + lane]), acc);
        p++;
    }
    // 8 edges per iteration: 4 int4 index loads + 8 gather loads in flight
    for (; p + 8 <= pe; p += 8) {
        const int4* q = reinterpret_cast<const int4*>(&d_epack[p]);
        int4 a = __ldg(&q[0]);   // edges p, p+1
        int4 b = __ldg(&q[1]);   // edges p+2, p+3
        int4 c = __ldg(&q[2]);   // edges p+4, p+5
        int4 d = __ldg(&q[3]);   // edges p+6, p+7
        float v0 = __ldg(&src[a.x * F + lane]);
        float v1 = __ldg(&src[a.z * F + lane]);
        float v2 = __ldg(&src[b.x * F + lane]);
        float v3 = __ldg(&src[b.z * F + lane]);
        float v4 = __ldg(&src[c.x * F + lane]);
        float v5 = __ldg(&src[c.z * F + lane]);
        float v6 = __ldg(&src[d.x * F + lane]);
        float v7 = __ldg(&src[d.z * F + lane]);
        acc = fmaf(__int_as_float(a.y), v0, acc);
        acc = fmaf(__int_as_float(a.w), v1, acc);
        acc = fmaf(__int_as_float(b.y), v2, acc);
        acc = fmaf(__int_as_float(b.w), v3, acc);
        acc = fmaf(__int_as_float(c.y), v4, acc);
        acc = fmaf(__int_as_float(c.w), v5, acc);
        acc = fmaf(__int_as_float(d.y), v6, acc);
        acc = fmaf(__int_as_float(d.w), v7, acc);
    }
    for (; p < pe; p++) {
        int2 e = d_epack[p];
        acc = fmaf(__int_as_float(e.y), __ldg(&src[e.x * F + lane]), acc);
    }
    dst[w * F + lane] = acc;
}

// fused Chebyshev combine + per-graph max pool.
// h = x@(W0-W2) + Tx1@W1 + P2@(2*W2) + b ; pooled via running max (batch sorted)
__global__ void __launch_bounds__(256) k_combine(
    const float* __restrict__ x,
    const int* __restrict__ batch,
    const float* __restrict__ Wc,
    const float* __restrict__ bc,
    int n)
{
    int lane = threadIdx.x & 31;
    int warp = threadIdx.x >> 5;

    float w0r[32], w1r[32], w2r[32];
#pragma unroll
    for (int i = 0; i < 32; i++) {
        float a = __ldg(&Wc[i * 32 + lane]);
        float b = __ldg(&Wc[1024 + i * 32 + lane]);
        float c = __ldg(&Wc[2048 + i * 32 + lane]);
        w0r[i] = a - c;
        w1r[i] = b;
        w2r[i] = 2.f * c;
    }
    float bias = __ldg(&bc[lane]);

    int n0 = blockIdx.x * NPB;
    int n1 = min(n0 + NPB, n);

    float runmax = __int_as_float(0xff800000);
    int curg = -1;

    for (int nn = n0 + warp; nn < n1; nn += 8) {
        float xv  = x[nn * F + lane];
        float t1v = d_t1[nn * F + lane];
        float p2v = d_p2[nn * F + lane];
        float acc = bias;
#pragma unroll
        for (int i = 0; i < 32; i++) {
            acc = fmaf(__shfl_sync(0xffffffffu, xv,  i), w0r[i], acc);
            acc = fmaf(__shfl_sync(0xffffffffu, t1v, i), w1r[i], acc);
            acc = fmaf(__shfl_sync(0xffffffffu, p2v, i), w2r[i], acc);
        }
        int gb = batch[nn];
        if (gb != curg) {
            if (curg >= 0) atomicMax(&d_pool[curg * F + lane], fenc(runmax));
            curg = gb;
            runmax = acc;
        } else {
            runmax = fmaxf(runmax, acc);
        }
    }
    if (curg >= 0) atomicMax(&d_pool[curg * F + lane], fenc(runmax));
}

__global__ void k_mlp1(const float* __restrict__ W1, const float* __restrict__ b1) {
    int t = blockIdx.x * blockDim.x + threadIdx.x;
    int b = t >> 10;
    int o = t & 1023;
    float acc = __ldg(&b1[o]);
#pragma unroll
    for (int i = 0; i < 32; i++) {
        float g = fdec(d_pool[b * 32 + i]);
        acc = fmaf(g, __ldg(&W1[i * 1024 + o]), acc);
    }
    d_h1[t] = fmaxf(acc, 0.f);
}

__global__ void k_mlp2(const float* __restrict__ W2, const float* __restrict__ b2) {
    __shared__ float h1s[64 * 129];
    __shared__ float w2s[128 * 8];
    int t = threadIdx.x;
    int o0 = blockIdx.x * 8;
    int b = t >> 2;
    int jo = t & 3;
    float a0 = 0.f, a1 = 0.f;

    for (int kt = 0; kt < 1024; kt += 128) {
        for (int l = t; l < 64 * 128; l += 256) {
            int r = l >> 7, c = l & 127;
            h1s[r * 129 + c] = d_h1[r * 1024 + kt + c];
        }
        for (int l = t; l < 1024; l += 256) {
            int k = l >> 3, j = l & 7;
            w2s[l] = __ldg(&W2[(kt + k) * 512 + o0 + j]);
        }
        __syncthreads();
#pragma unroll
        for (int k = 0; k < 128; k++) {
            float h = h1s[b * 129 + k];
            a0 = fmaf(h, w2s[k * 8 + jo], a0);
            a1 = fmaf(h, w2s[k * 8 + jo + 4], a1);
        }
        __syncthreads();
    }
    d_h2[b * 512 + o0 + jo]     = fmaxf(a0 + __ldg(&b2[o0 + jo]), 0.f);
    d_h2[b * 512 + o0 + jo + 4] = fmaxf(a1 + __ldg(&b2[o0 + jo + 4]), 0.f);
}

__global__ void k_mlp3(const float* __restrict__ W3, const float* __restrict__ b3,
                       float* __restrict__ out) {
    int w = blockIdx.x * (blockDim.x >> 5) + (threadIdx.x >> 5);
    int lane = threadIdx.x & 31;
    if (w >= 256) return;
    int b = w >> 2;
    int o = w & 3;
    float s = 0.f;
    for (int k = lane; k < 512; k += 32)
        s = fmaf(d_h2[b * 512 + k], __ldg(&W3[k * 4 + o]), s);
#pragma unroll
    for (int off = 16; off; off >>= 1)
        s += __shfl_xor_sync(0xffffffffu, s, off);
    if (lane == 0) out[b * 4 + o] = s + __ldg(&b3[o]);
}

// ---------------- launch ----------------
extern "C" void kernel_launch(void* const* d_in, const int* in_sizes, int n_in,
                              void* d_out, int out_size) {
    const float* x     = (const float*)d_in[0];
    const int*   ei    = (const int*)d_in[1];
    const int*   batch = (const int*)d_in[2];
    const float* Wc    = (const float*)d_in[3];
    const float* bc    = (const float*)d_in[4];
    const float* W1    = (const float*)d_in[5];
    const float* b1    = (const float*)d_in[6];
    const float* W2    = (const float*)d_in[7];
    const float* b2    = (const float*)d_in[8];
    const float* W3    = (const float*)d_in[9];
    const float* b3    = (const float*)d_in[10];

    int N = in_sizes[0] / F;
    int E = in_sizes[1] / 2;

    void *t1p = nullptr, *p2p = nullptr;
    cudaGetSymbolAddress(&t1p, d_t1);
    cudaGetSymbolAddress(&p2p, d_p2);

    int nblk_scan = (N + SCANB - 1) / SCANB;   // 98 for N=100000

    k_init<<<(N + 255) / 256, 256>>>(N);
    k_count<<<(E + 255) / 256, 256>>>(ei, E);
    k_scan1<<<nblk_scan, SCANB>>>(N);
    k_scan2<<<1, 128>>>(nblk_scan);
    k_scan3<<<nblk_scan, SCANB>>>(N, E);
    k_scatter<<<(E + 255) / 256, 256>>>(ei, E);

    int gth_blocks = (N * 32 + 255) / 256;
    k_gather<<<gth_blocks, 256>>>(x, (float*)t1p, N);
    k_gather<<<gth_blocks, 256>>>((const float*)t1p, (float*)p2p, N);

    k_combine<<<(N + NPB - 1) / NPB, 256>>>(x, batch, Wc, bc, N);

    k_mlp1<<<256, 256>>>(W1, b1);
    k_mlp2<<<64, 256>>>(W2, b2);
    k_mlp3<<<32, 256>>>(W3, b3, (float*)d_out);
}

// round 11
// speedup vs baseline: 1.4365x; 1.4365x over previous
#include <cuda_runtime.h>
#include <cuda_bf16.h>

#define NMAX 100000
#define EMAX 1600000
#define F 32
#define NG 64
#define NPB 128
#define SCANB 1024

// ---------------- scratch (static device globals; no allocs) ----------------
__device__ int2     d_epack[EMAX];     // CSR-ordered (src_row, nrm-as-int)
__device__ int      d_degr[NMAX];      // out-degree (segment_sum over row)
__device__ int      d_cnt[NMAX];       // in-count per col (CSR sizes)
__device__ int      d_ptr[NMAX + 1];   // CSR offsets
__device__ int      d_fill[NMAX];      // running fill pointers
__device__ int      d_bsum[128];
__device__ int      d_boff[128];
__device__ float    d_t1[NMAX * F];    // Tx1 = prop(x)
__device__ float    d_p2[NMAX * F];    // P2  = prop(Tx1)
__device__ unsigned d_pool[NG * F];    // segment-max, order-preserving uint encoding
__device__ float    d_h1[NG * 1024];
__device__ float    d_h2[NG * 512];

__device__ __forceinline__ unsigned fenc(float f) {
    unsigned b = __float_as_uint(f);
    return (b & 0x80000000u) ? ~b : (b | 0x80000000u);
}
__device__ __forceinline__ float fdec(unsigned u) {
    return __uint_as_float((u & 0x80000000u) ? (u & 0x7FFFFFFFu) : ~u);
}

// ---------------- kernels ----------------

__global__ void k_init(int n) {
    int i = blockIdx.x * blockDim.x + threadIdx.x;
    if (i < n) { d_degr[i] = 0; d_cnt[i] = 0; }
    if (i < NG * F) d_pool[i] = 0x007FFFFFu;  // fenc(-inf)
}

// edge_index is int32. Count row-degree and col-incount directly from ei.
__global__ void k_count(const int* __restrict__ ei, int E) {
    int e = blockIdx.x * blockDim.x + threadIdx.x;
    if (e >= E) return;
    atomicAdd(&d_degr[ei[e]], 1);        // REDG (result unused)
    atomicAdd(&d_cnt[ei[E + e]], 1);
}

// exclusive prefix scan of d_cnt -> d_ptr (3-phase)
__global__ void k_scan1(int n) {
    __shared__ int s[SCANB];
    int i = blockIdx.x * SCANB + threadIdx.x;
    int v = (i < n) ? d_cnt[i] : 0;
    s[threadIdx.x] = v;
    __syncthreads();
#pragma unroll
    for (int off = 1; off < SCANB; off <<= 1) {
        int t = (threadIdx.x >= off) ? s[threadIdx.x - off] : 0;
        __syncthreads();
        s[threadIdx.x] += t;
        __syncthreads();
    }
    if (i < n) d_ptr[i] = s[threadIdx.x] - v;  // exclusive
    if (threadIdx.x == SCANB - 1) d_bsum[blockIdx.x] = s[SCANB - 1];
}

// parallel exclusive scan of <=128 block sums
__global__ void k_scan2(int nb) {
    __shared__ int s[128];
    int t = threadIdx.x;
    int v = (t < nb) ? d_bsum[t] : 0;
    s[t] = v;
    __syncthreads();
#pragma unroll
    for (int off = 1; off < 128; off <<= 1) {
        int u = (t >= off) ? s[t - off] : 0;
        __syncthreads();
        s[t] += u;
        __syncthreads();
    }
    if (t < nb) d_boff[t] = s[t] - v;   // exclusive
}

__global__ void k_scan3(int n, int E) {
    int i = blockIdx.x * SCANB + threadIdx.x;
    if (i < n) {
        int p = d_ptr[i] + d_boff[blockIdx.x];
        d_ptr[i] = p;
        d_fill[i] = p;
    }
    if (i == 0) d_ptr[n] = E;
}

// scatter edges into CSR slots, computing nrm on the fly (reads ei directly)
__global__ void k_scatter(const int* __restrict__ ei, int E) {
    int e = blockIdx.x * blockDim.x + threadIdx.x;
    if (e >= E) return;
    int r = ei[e];
    int c = ei[E + e];
    int dr = d_degr[r];
    int dc = d_degr[c];
    float fr = (dr > 0) ? rsqrtf((float)dr) : 0.f;
    float fc = (dc > 0) ? rsqrtf((float)dc) : 0.f;
    float nrm = -(fr * fc);
    int p = atomicAdd(&d_fill[c], 1);
    d_epack[p] = make_int2(r, __float_as_int(nrm));
}

// gather propagation: dst[c] = sum_{e in CSR[c]} nrm_e * src[row_e]; warp/node
// (R9 unroll-4 form — known-good: 4 independent gather lines in flight/warp)
__global__ void __launch_bounds__(256) k_gather(const float* __restrict__ src,
                                                float* __restrict__ dst, int n) {
    int w = (blockIdx.x * blockDim.x + threadIdx.x) >> 5;
    int lane = threadIdx.x & 31;
    if (w >= n) return;
    int p = d_ptr[w];
    int pe = d_ptr[w + 1];
    float acc = 0.f;
    for (; p + 4 <= pe; p += 4) {
        int2 e0 = d_epack[p];
        int2 e1 = d_epack[p + 1];
        int2 e2 = d_epack[p + 2];
        int2 e3 = d_epack[p + 3];
        float v0 = __ldg(&src[e0.x * F + lane]);
        float v1 = __ldg(&src[e1.x * F + lane]);
        float v2 = __ldg(&src[e2.x * F + lane]);
        float v3 = __ldg(&src[e3.x * F + lane]);
        acc = fmaf(__int_as_float(e0.y), v0, acc);
        acc = fmaf(__int_as_float(e1.y), v1, acc);
        acc = fmaf(__int_as_float(e2.y), v2, acc);
        acc = fmaf(__int_as_float(e3.y), v3, acc);
    }
    for (; p < pe; p++) {
        int2 e = d_epack[p];
        acc = fmaf(__int_as_float(e.y), __ldg(&src[e.x * F + lane]), acc);
    }
    dst[w * F + lane] = acc;
}

// fused Chebyshev combine + per-graph max pool.
// h = x@(W0-W2) + Tx1@W1 + P2@(2*W2) + b ; pooled via running max (batch sorted)
__global__ void __launch_bounds__(256) k_combine(
    const float* __restrict__ x,
    const int* __restrict__ batch,
    const float* __restrict__ Wc,
    const float* __restrict__ bc,
    int n)
{
    int lane = threadIdx.x & 31;
    int warp = threadIdx.x >> 5;

    float w0r[32], w1r[32], w2r[32];
#pragma unroll
    for (int i = 0; i < 32; i++) {
        float a = __ldg(&Wc[i * 32 + lane]);
        float b = __ldg(&Wc[1024 + i * 32 + lane]);
        float c = __ldg(&Wc[2048 + i * 32 + lane]);
        w0r[i] = a - c;
        w1r[i] = b;
        w2r[i] = 2.f * c;
    }
    float bias = __ldg(&bc[lane]);

    int n0 = blockIdx.x * NPB;
    int n1 = min(n0 + NPB, n);

    float runmax = __int_as_float(0xff800000);
    int curg = -1;

    for (int nn = n0 + warp; nn < n1; nn += 8) {
        float xv  = x[nn * F + lane];
        float t1v = d_t1[nn * F + lane];
        float p2v = d_p2[nn * F + lane];
        float acc = bias;
#pragma unroll
        for (int i = 0; i < 32; i++) {
            acc = fmaf(__shfl_sync(0xffffffffu, xv,  i), w0r[i], acc);
            acc = fmaf(__shfl_sync(0xffffffffu, t1v, i), w1r[i], acc);
            acc = fmaf(__shfl_sync(0xffffffffu, p2v, i), w2r[i], acc);
        }
        int gb = batch[nn];
        if (gb != curg) {
            if (curg >= 0) atomicMax(&d_pool[curg * F + lane], fenc(runmax));
            curg = gb;
            runmax = acc;
        } else {
            runmax = fmaxf(runmax, acc);
        }
    }
    if (curg >= 0) atomicMax(&d_pool[curg * F + lane], fenc(runmax));
}

__global__ void k_mlp1(const float* __restrict__ W1, const float* __restrict__ b1) {
    int t = blockIdx.x * blockDim.x + threadIdx.x;
    int b = t >> 10;
    int o = t & 1023;
    float acc = __ldg(&b1[o]);
#pragma unroll
    for (int i = 0; i < 32; i++) {
        float g = fdec(d_pool[b * 32 + i]);
        acc = fmaf(g, __ldg(&W1[i * 1024 + o]), acc);
    }
    d_h1[t] = fmaxf(acc, 0.f);
}

__global__ void k_mlp2(const float* __restrict__ W2, const float* __restrict__ b2) {
    __shared__ float h1s[64 * 129];
    __shared__ float w2s[128 * 8];
    int t = threadIdx.x;
    int o0 = blockIdx.x * 8;
    int b = t >> 2;
    int jo = t & 3;
    float a0 = 0.f, a1 = 0.f;

    for (int kt = 0; kt < 1024; kt += 128) {
        for (int l = t; l < 64 * 128; l += 256) {
            int r = l >> 7, c = l & 127;
            h1s[r * 129 + c] = d_h1[r * 1024 + kt + c];
        }
        for (int l = t; l < 1024; l += 256) {
            int k = l >> 3, j = l & 7;
            w2s[l] = __ldg(&W2[(kt + k) * 512 + o0 + j]);
        }
        __syncthreads();
#pragma unroll
        for (int k = 0; k < 128; k++) {
            float h = h1s[b * 129 + k];
            a0 = fmaf(h, w2s[k * 8 + jo], a0);
            a1 = fmaf(h, w2s[k * 8 + jo + 4], a1);
        }
        __syncthreads();
    }
    d_h2[b * 512 + o0 + jo]     = fmaxf(a0 + __ldg(&b2[o0 + jo]), 0.f);
    d_h2[b * 512 + o0 + jo + 4] = fmaxf(a1 + __ldg(&b2[o0 + jo + 4]), 0.f);
}

__global__ void k_mlp3(const float* __restrict__ W3, const float* __restrict__ b3,
                       float* __restrict__ out) {
    int w = blockIdx.x * (blockDim.x >> 5) + (threadIdx.x >> 5);
    int lane = threadIdx.x & 31;
    if (w >= 256) return;
    int b = w >> 2;
    int o = w & 3;
    float s = 0.f;
    for (int k = lane; k < 512; k += 32)
        s = fmaf(d_h2[b * 512 + k], __ldg(&W3[k * 4 + o]), s);
#pragma unroll
    for (int off = 16; off; off >>= 1)
        s += __shfl_xor_sync(0xffffffffu, s, off);
    if (lane == 0) out[b * 4 + o] = s + __ldg(&b3[o]);
}

// ---------------- launch ----------------
extern "C" void kernel_launch(void* const* d_in, const int* in_sizes, int n_in,
                              void* d_out, int out_size) {
    const float* x     = (const float*)d_in[0];
    const int*   ei    = (const int*)d_in[1];
    const int*   batch = (const int*)d_in[2];
    const float* Wc    = (const float*)d_in[3];
    const float* bc    = (const float*)d_in[4];
    const float* W1    = (const float*)d_in[5];
    const float* b1    = (const float*)d_in[6];
    const float* W2    = (const float*)d_in[7];
    const float* b2    = (const float*)d_in[8];
    const float* W3    = (const float*)d_in[9];
    const float* b3    = (const float*)d_in[10];

    int N = in_sizes[0] / F;
    int E = in_sizes[1] / 2;

    void *t1p = nullptr, *p2p = nullptr;
    cudaGetSymbolAddress(&t1p, d_t1);
    cudaGetSymbolAddress(&p2p, d_p2);

    int nblk_scan = (N + SCANB - 1) / SCANB;   // 98 for N=100000

    k_init<<<(N + 255) / 256, 256>>>(N);
    k_count<<<(E + 255) / 256, 256>>>(ei, E);
    k_scan1<<<nblk_scan, SCANB>>>(N);
    k_scan2<<<1, 128>>>(nblk_scan);
    k_scan3<<<nblk_scan, SCANB>>>(N, E);
    k_scatter<<<(E + 255) / 256, 256>>>(ei, E);

    int gth_blocks = (N * 32 + 255) / 256;
    k_gather<<<gth_blocks, 256>>>(x, (float*)t1p, N);
    k_gather<<<gth_blocks, 256>>>((const float*)t1p, (float*)p2p, N);

    k_combine<<<(N + NPB - 1) / NPB, 256>>>(x, batch, Wc, bc, N);

    k_mlp1<<<256, 256>>>(W1, b1);
    k_mlp2<<<64, 256>>>(W2, b2);
    k_mlp3<<<32, 256>>>(W3, b3, (float*)d_out);
}

// round 12
// speedup vs baseline: 1.5063x; 1.0486x over previous
#include <cuda_runtime.h>
#include <cuda_bf16.h>

#define NMAX 100000
#define EMAX 1600000
#define F 32
#define NG 64
#define SCANB 1024

// ---------------- scratch (static device globals; no allocs) ----------------
__device__ int2     d_epack[EMAX];     // CSR-ordered (src_row, nrm-as-int)
__device__ int      d_degr[NMAX];      // out-degree (segment_sum over row)
__device__ int      d_cnt[NMAX];       // in-count per col (CSR sizes)
__device__ int      d_ptr[NMAX + 1];   // CSR offsets
__device__ int      d_fill[NMAX];      // running fill pointers
__device__ int      d_bsum[128];
__device__ float    d_t1[NMAX * F];    // Tx1 = prop(x)
__device__ float    d_p2[NMAX * F];    // P2  = prop(Tx1)
__device__ unsigned d_pool[NG * F];    // segment-max, order-preserving uint encoding
__device__ float    d_h1[NG * 1024];
__device__ float    d_h2[NG * 512];

__device__ __forceinline__ unsigned fenc(float f) {
    unsigned b = __float_as_uint(f);
    return (b & 0x80000000u) ? ~b : (b | 0x80000000u);
}
__device__ __forceinline__ float fdec(unsigned u) {
    return __uint_as_float((u & 0x80000000u) ? (u & 0x7FFFFFFFu) : ~u);
}

// ---------------- kernels ----------------

__global__ void k_init(int n) {
    int i = blockIdx.x * blockDim.x + threadIdx.x;
    if (i < n) { d_degr[i] = 0; d_cnt[i] = 0; }
    if (i < NG * F) d_pool[i] = 0x007FFFFFu;  // fenc(-inf)
}

__global__ void k_count(const int* __restrict__ ei, int E) {
    int e = blockIdx.x * blockDim.x + threadIdx.x;
    if (e >= E) return;
    atomicAdd(&d_degr[ei[e]], 1);        // REDG (result unused)
    atomicAdd(&d_cnt[ei[E + e]], 1);
}

// per-block exclusive scan of d_cnt -> d_ptr (local), block sums to d_bsum
__global__ void k_scan1(int n) {
    __shared__ int s[SCANB];
    int i = blockIdx.x * SCANB + threadIdx.x;
    int v = (i < n) ? d_cnt[i] : 0;
    s[threadIdx.x] = v;
    __syncthreads();
#pragma unroll
    for (int off = 1; off < SCANB; off <<= 1) {
        int t = (threadIdx.x >= off) ? s[threadIdx.x - off] : 0;
        __syncthreads();
        s[threadIdx.x] += t;
        __syncthreads();
    }
    if (i < n) d_ptr[i] = s[threadIdx.x] - v;  // exclusive within block
    if (threadIdx.x == SCANB - 1) d_bsum[blockIdx.x] = s[SCANB - 1];
}

// fused: each block reduces its bsum prefix, then applies offset (was scan2+scan3)
__global__ void k_scan3(int n, int E) {
    __shared__ int red[32];
    __shared__ int offsh;
    int t = threadIdx.x;
    int v = (t < blockIdx.x && t < 128) ? d_bsum[t] : 0;
#pragma unroll
    for (int o = 16; o; o >>= 1) v += __shfl_xor_sync(0xffffffffu, v, o);
    if ((t & 31) == 0) red[t >> 5] = v;
    __syncthreads();
    if (t < 32) {
        int r = red[t];
#pragma unroll
        for (int o = 16; o; o >>= 1) r += __shfl_xor_sync(0xffffffffu, r, o);
        if (t == 0) offsh = r;
    }
    __syncthreads();
    int off = offsh;
    int i = blockIdx.x * SCANB + t;
    if (i < n) {
        int p = d_ptr[i] + off;
        d_ptr[i] = p;
        d_fill[i] = p;
    }
    if (i == 0) d_ptr[n] = E;
}

// scatter edges into CSR slots, computing nrm on the fly
__global__ void k_scatter(const int* __restrict__ ei, int E) {
    int e = blockIdx.x * blockDim.x + threadIdx.x;
    if (e >= E) return;
    int r = ei[e];
    int c = ei[E + e];
    int dr = d_degr[r];
    int dc = d_degr[c];
    float fr = (dr > 0) ? rsqrtf((float)dr) : 0.f;
    float fc = (dc > 0) ? rsqrtf((float)dc) : 0.f;
    float nrm = -(fr * fc);
    int p = atomicAdd(&d_fill[c], 1);
    d_epack[p] = make_int2(r, __float_as_int(nrm));
}

// gather propagation, software-pipelined: prefetch next 4 edge records while
// current 4 gather lines are in flight. warp/node, lane = feature.
__global__ void __launch_bounds__(256) k_gather(const float* __restrict__ src,
                                                float* __restrict__ dst, int n) {
    int w = (blockIdx.x * blockDim.x + threadIdx.x) >> 5;
    int lane = threadIdx.x & 31;
    if (w >= n) return;
    int p = d_ptr[w];
    int pe = d_ptr[w + 1];
    float acc = 0.f;

    if (p + 4 <= pe) {
        int2 e0 = d_epack[p];
        int2 e1 = d_epack[p + 1];
        int2 e2 = d_epack[p + 2];
        int2 e3 = d_epack[p + 3];
        for (; p + 8 <= pe; p += 4) {
            int2 n0 = d_epack[p + 4];
            int2 n1 = d_epack[p + 5];
            int2 n2 = d_epack[p + 6];
            int2 n3 = d_epack[p + 7];
            float v0 = __ldg(&src[e0.x * F + lane]);
            float v1 = __ldg(&src[e1.x * F + lane]);
            float v2 = __ldg(&src[e2.x * F + lane]);
            float v3 = __ldg(&src[e3.x * F + lane]);
            acc = fmaf(__int_as_float(e0.y), v0, acc);
            acc = fmaf(__int_as_float(e1.y), v1, acc);
            acc = fmaf(__int_as_float(e2.y), v2, acc);
            acc = fmaf(__int_as_float(e3.y), v3, acc);
            e0 = n0; e1 = n1; e2 = n2; e3 = n3;
        }
        float v0 = __ldg(&src[e0.x * F + lane]);
        float v1 = __ldg(&src[e1.x * F + lane]);
        float v2 = __ldg(&src[e2.x * F + lane]);
        float v3 = __ldg(&src[e3.x * F + lane]);
        acc = fmaf(__int_as_float(e0.y), v0, acc);
        acc = fmaf(__int_as_float(e1.y), v1, acc);
        acc = fmaf(__int_as_float(e2.y), v2, acc);
        acc = fmaf(__int_as_float(e3.y), v3, acc);
        p += 4;
    }
    for (; p < pe; p++) {
        int2 e = d_epack[p];
        acc = fmaf(__int_as_float(e.y), __ldg(&src[e.x * F + lane]), acc);
    }
    dst[w * F + lane] = acc;
}

// 32-wide matvec accumulate: acc[o] += row[i] * ws[i*32+o]
// row values are per-thread registers; weights are warp-uniform LDS.128 broadcasts.
__device__ __forceinline__ void mv32(const float* __restrict__ row,
                                     const float* __restrict__ ws,
                                     float acc[32]) {
    const float4* r4 = reinterpret_cast<const float4*>(row);
#pragma unroll 2
    for (int c = 0; c < 8; c++) {
        float4 v = __ldg(&r4[c]);
        float vv[4] = {v.x, v.y, v.z, v.w};
#pragma unroll
        for (int j = 0; j < 4; j++) {
            const float4* w4 = reinterpret_cast<const float4*>(&ws[(c * 4 + j) * 32]);
#pragma unroll
            for (int ob = 0; ob < 8; ob++) {
                float4 wv = w4[ob];
                acc[ob * 4 + 0] = fmaf(vv[j], wv.x, acc[ob * 4 + 0]);
                acc[ob * 4 + 1] = fmaf(vv[j], wv.y, acc[ob * 4 + 1]);
                acc[ob * 4 + 2] = fmaf(vv[j], wv.z, acc[ob * 4 + 2]);
                acc[ob * 4 + 3] = fmaf(vv[j], wv.w, acc[ob * 4 + 3]);
            }
        }
    }
}

// node-per-thread Chebyshev combine + per-graph max pool.
// h = x@(W0-W2) + Tx1@W1 + P2@(2*W2) + b
__global__ void __launch_bounds__(256) k_combine(
    const float* __restrict__ x,
    const int* __restrict__ batch,
    const float* __restrict__ Wc,
    const float* __restrict__ bc,
    int n)
{
    __shared__ float ws[96 * 32];   // rows 0-31: W0-W2, 32-63: W1, 64-95: 2*W2
    __shared__ float bs[32];
    int t = threadIdx.x;

    for (int l = t; l < 1024; l += 256) {
        int i = l >> 5, o = l & 31;
        float w0 = __ldg(&Wc[i * 32 + o]);
        float w1 = __ldg(&Wc[1024 + i * 32 + o]);
        float w2 = __ldg(&Wc[2048 + i * 32 + o]);
        ws[i * 32 + o] = w0 - w2;
        ws[(32 + i) * 32 + o] = w1;
        ws[(64 + i) * 32 + o] = 2.f * w2;
    }
    if (t < 32) bs[t] = __ldg(&bc[t]);
    __syncthreads();

    int nidx = blockIdx.x * 256 + t;
    int lane = t & 31;
    bool valid = nidx < n;

    float acc[32];
#pragma unroll
    for (int o = 0; o < 32; o++) acc[o] = bs[o];

    if (valid) {
        mv32(x + (long long)nidx * 32, ws, acc);
        mv32(d_t1 + (long long)nidx * 32, ws + 32 * 32, acc);
        mv32(d_p2 + (long long)nidx * 32, ws + 64 * 32, acc);
    }

    int g = valid ? batch[nidx] : -1;
    unsigned vm = __ballot_sync(0xffffffffu, valid);
    int gfirst = __shfl_sync(0xffffffffu, g, 0);
    int glast  = __shfl_sync(0xffffffffu, g, 31);

    if (vm == 0xffffffffu && gfirst == glast) {
        // whole warp same graph: transpose-reduce — feature o max over 32 nodes
        float myv = 0.f;
#pragma unroll
        for (int o = 0; o < 32; o++) {
            float r = acc[o];
#pragma unroll
            for (int off = 16; off; off >>= 1)
                r = fmaxf(r, __shfl_xor_sync(0xffffffffu, r, off));
            if (lane == o) myv = r;
        }
        atomicMax(&d_pool[gfirst * F + lane], fenc(myv));
    } else if (valid) {
#pragma unroll
        for (int o = 0; o < 32; o++)
            atomicMax(&d_pool[g * F + o], fenc(acc[o]));
    }
}

__global__ void k_mlp1(const float* __restrict__ W1, const float* __restrict__ b1) {
    int t = blockIdx.x * blockDim.x + threadIdx.x;
    int b = t >> 10;
    int o = t & 1023;
    float acc = __ldg(&b1[o]);
#pragma unroll
    for (int i = 0; i < 32; i++) {
        float g = fdec(d_pool[b * 32 + i]);
        acc = fmaf(g, __ldg(&W1[i * 1024 + o]), acc);
    }
    d_h1[t] = fmaxf(acc, 0.f);
}

__global__ void k_mlp2(const float* __restrict__ W2, const float* __restrict__ b2) {
    __shared__ float h1s[64 * 129];
    __shared__ float w2s[128 * 8];
    int t = threadIdx.x;
    int o0 = blockIdx.x * 8;
    int b = t >> 2;
    int jo = t & 3;
    float a0 = 0.f, a1 = 0.f;

    for (int kt = 0; kt < 1024; kt += 128) {
        for (int l = t; l < 64 * 128; l += 256) {
            int r = l >> 7, c = l & 127;
            h1s[r * 129 + c] = d_h1[r * 1024 + kt + c];
        }
        for (int l = t; l < 1024; l += 256) {
            int k = l >> 3, j = l & 7;
            w2s[l] = __ldg(&W2[(kt + k) * 512 + o0 + j]);
        }
        __syncthreads();
#pragma unroll
        for (int k = 0; k < 128; k++) {
            float h = h1s[b * 129 + k];
            a0 = fmaf(h, w2s[k * 8 + jo], a0);
            a1 = fmaf(h, w2s[k * 8 + jo + 4], a1);
        }
        __syncthreads();
    }
    d_h2[b * 512 + o0 + jo]     = fmaxf(a0 + __ldg(&b2[o0 + jo]), 0.f);
    d_h2[b * 512 + o0 + jo + 4] = fmaxf(a1 + __ldg(&b2[o0 + jo + 4]), 0.f);
}

__global__ void k_mlp3(const float* __restrict__ W3, const float* __restrict__ b3,
                       float* __restrict__ out) {
    int w = blockIdx.x * (blockDim.x >> 5) + (threadIdx.x >> 5);
    int lane = threadIdx.x & 31;
    if (w >= 256) return;
    int b = w >> 2;
    int o = w & 3;
    float s = 0.f;
    for (int k = lane; k < 512; k += 32)
        s = fmaf(d_h2[b * 512 + k], __ldg(&W3[k * 4 + o]), s);
#pragma unroll
    for (int off = 16; off; off >>= 1)
        s += __shfl_xor_sync(0xffffffffu, s, off);
    if (lane == 0) out[b * 4 + o] = s + __ldg(&b3[o]);
}

// ---------------- launch ----------------
extern "C" void kernel_launch(void* const* d_in, const int* in_sizes, int n_in,
                              void* d_out, int out_size) {
    const float* x     = (const float*)d_in[0];
    const int*   ei    = (const int*)d_in[1];
    const int*   batch = (const int*)d_in[2];
    const float* Wc    = (const float*)d_in[3];
    const float* bc    = (const float*)d_in[4];
    const float* W1    = (const float*)d_in[5];
    const float* b1    = (const float*)d_in[6];
    const float* W2    = (const float*)d_in[7];
    const float* b2    = (const float*)d_in[8];
    const float* W3    = (const float*)d_in[9];
    const float* b3    = (const float*)d_in[10];

    int N = in_sizes[0] / F;
    int E = in_sizes[1] / 2;

    void *t1p = nullptr, *p2p = nullptr;
    cudaGetSymbolAddress(&t1p, d_t1);
    cudaGetSymbolAddress(&p2p, d_p2);

    int nblk_scan = (N + SCANB - 1) / SCANB;   // 98 for N=100000

    k_init<<<(N + 255) / 256, 256>>>(N);
    k_count<<<(E + 255) / 256, 256>>>(ei, E);
    k_scan1<<<nblk_scan, SCANB>>>(N);
    k_scan3<<<nblk_scan, SCANB>>>(N, E);
    k_scatter<<<(E + 255) / 256, 256>>>(ei, E);

    int gth_blocks = (N * 32 + 255) / 256;
    k_gather<<<gth_blocks, 256>>>(x, (float*)t1p, N);
    k_gather<<<gth_blocks, 256>>>((const float*)t1p, (float*)p2p, N);

    k_combine<<<(N + 255) / 256, 256>>>(x, batch, Wc, bc, N);

    k_mlp1<<<256, 256>>>(W1, b1);
    k_mlp2<<<64, 256>>>(W2, b2);
    k_mlp3<<<32, 256>>>(W3, b3, (float*)d_out);
}

// round 13
// speedup vs baseline: 1.5332x; 1.0178x over previous
#include <cuda_runtime.h>
#include <cuda_bf16.h>

#define NMAX 100000
#define EMAX 1600000
#define F 32
#define NG 64
#define SCANB 1024

// ---------------- scratch (static device globals; no allocs) ----------------
__device__ int2     d_epack[EMAX];     // CSR-ordered (src_row, nrm-as-int)
__device__ int      d_degr[NMAX];      // out-degree (segment_sum over row)
__device__ int      d_cnt[NMAX];       // in-count per col (CSR sizes)
__device__ int      d_ptr[NMAX + 1];   // CSR offsets
__device__ int      d_fill[NMAX];      // running fill pointers
__device__ int      d_bsum[128];
__device__ float    d_t1[NMAX * F];    // Tx1 = prop(x)
__device__ float    d_p2[NMAX * F];    // P2  = prop(Tx1)
__device__ unsigned d_pool[NG * F];    // segment-max, order-preserving uint encoding
__device__ float    d_h1[NG * 1024];
__device__ float    d_h2[NG * 512];

__device__ __forceinline__ unsigned fenc(float f) {
    unsigned b = __float_as_uint(f);
    return (b & 0x80000000u) ? ~b : (b | 0x80000000u);
}
__device__ __forceinline__ float fdec(unsigned u) {
    return __uint_as_float((u & 0x80000000u) ? (u & 0x7FFFFFFFu) : ~u);
}

// ---------------- kernels ----------------

__global__ void k_init(int n) {
    int i = blockIdx.x * blockDim.x + threadIdx.x;
    if (i < n) { d_degr[i] = 0; d_cnt[i] = 0; }
    if (i < NG * F) d_pool[i] = 0x007FFFFFu;  // fenc(-inf)
}

__global__ void k_count(const int* __restrict__ ei, int E) {
    int e = blockIdx.x * blockDim.x + threadIdx.x;
    if (e >= E) return;
    atomicAdd(&d_degr[ei[e]], 1);        // REDG (result unused)
    atomicAdd(&d_cnt[ei[E + e]], 1);
}

// per-block exclusive scan of d_cnt -> d_ptr (local), block sums to d_bsum
__global__ void k_scan1(int n) {
    __shared__ int s[SCANB];
    int i = blockIdx.x * SCANB + threadIdx.x;
    int v = (i < n) ? d_cnt[i] : 0;
    s[threadIdx.x] = v;
    __syncthreads();
#pragma unroll
    for (int off = 1; off < SCANB; off <<= 1) {
        int t = (threadIdx.x >= off) ? s[threadIdx.x - off] : 0;
        __syncthreads();
        s[threadIdx.x] += t;
        __syncthreads();
    }
    if (i < n) d_ptr[i] = s[threadIdx.x] - v;  // exclusive within block
    if (threadIdx.x == SCANB - 1) d_bsum[blockIdx.x] = s[SCANB - 1];
}

// fused: each block reduces its bsum prefix, then applies offset
__global__ void k_scan3(int n, int E) {
    __shared__ int red[32];
    __shared__ int offsh;
    int t = threadIdx.x;
    int v = (t < blockIdx.x && t < 128) ? d_bsum[t] : 0;
#pragma unroll
    for (int o = 16; o; o >>= 1) v += __shfl_xor_sync(0xffffffffu, v, o);
    if ((t & 31) == 0) red[t >> 5] = v;
    __syncthreads();
    if (t < 32) {
        int r = red[t];
#pragma unroll
        for (int o = 16; o; o >>= 1) r += __shfl_xor_sync(0xffffffffu, r, o);
        if (t == 0) offsh = r;
    }
    __syncthreads();
    int off = offsh;
    int i = blockIdx.x * SCANB + t;
    if (i < n) {
        int p = d_ptr[i] + off;
        d_ptr[i] = p;
        d_fill[i] = p;
    }
    if (i == 0) d_ptr[n] = E;
}

// scatter edges into CSR slots, computing nrm on the fly
__global__ void k_scatter(const int* __restrict__ ei, int E) {
    int e = blockIdx.x * blockDim.x + threadIdx.x;
    if (e >= E) return;
    int r = ei[e];
    int c = ei[E + e];
    int dr = d_degr[r];
    int dc = d_degr[c];
    float fr = (dr > 0) ? rsqrtf((float)dr) : 0.f;
    float fc = (dc > 0) ? rsqrtf((float)dc) : 0.f;
    float nrm = -(fr * fc);
    int p = atomicAdd(&d_fill[c], 1);
    d_epack[p] = make_int2(r, __float_as_int(nrm));
}

// half-warp dual-edge gather: warp per node, lanes 0-15 = edge A, 16-31 = edge B,
// each lane covers 2 features (float2). Per 2 edges: 1 int4 edge load + 1 LDG.64
// value load -> halves LDG instruction count vs warp-per-edge.
__global__ void __launch_bounds__(256) k_gather(const float* __restrict__ src,
                                                float* __restrict__ dst, int n) {
    int w = (blockIdx.x * blockDim.x + threadIdx.x) >> 5;
    int lane = threadIdx.x & 31;
    if (w >= n) return;
    int p = d_ptr[w];
    int pe = d_ptr[w + 1];
    int half = lane >> 4;        // 0: edge A, 1: edge B
    int fl = lane & 15;          // feature pair index (features 2*fl, 2*fl+1)

    float ax = 0.f, ay = 0.f;

    // head: align p to even for int4 loads (half 0 only processes the odd record)
    if ((p & 1) && p < pe) {
        if (half == 0) {
            int2 e = d_epack[p];
            float2 v = __ldg((const float2*)(src + e.x * F) + fl);
            float nm = __int_as_float(e.y);
            ax = fmaf(nm, v.x, ax);
            ay = fmaf(nm, v.y, ay);
        }
        p++;
    }
    // main: 4 edges per iteration (2 aligned int4 record loads)
    for (; p + 4 <= pe; p += 4) {
        int4 r0 = *(const int4*)&d_epack[p];       // edges p, p+1 (broadcast)
        int4 r1 = *(const int4*)&d_epack[p + 2];   // edges p+2, p+3
        int   s0 = half ? r0.z : r0.x;
        float m0 = __int_as_float(half ? r0.w : r0.y);
        int   s1 = half ? r1.z : r1.x;
        float m1 = __int_as_float(half ? r1.w : r1.y);
        float2 v0 = __ldg((const float2*)(src + s0 * F) + fl);
        float2 v1 = __ldg((const float2*)(src + s1 * F) + fl);
        ax = fmaf(m0, v0.x, ax);
        ay = fmaf(m0, v0.y, ay);
        ax = fmaf(m1, v1.x, ax);
        ay = fmaf(m1, v1.y, ay);
    }
    // 2-edge step
    if (p + 2 <= pe) {
        int4 r0 = *(const int4*)&d_epack[p];
        int   s0 = half ? r0.z : r0.x;
        float m0 = __int_as_float(half ? r0.w : r0.y);
        float2 v0 = __ldg((const float2*)(src + s0 * F) + fl);
        ax = fmaf(m0, v0.x, ax);
        ay = fmaf(m0, v0.y, ay);
        p += 2;
    }
    // tail: single remaining record (half 0 only)
    if (p < pe && half == 0) {
        int2 e = d_epack[p];
        float2 v = __ldg((const float2*)(src + e.x * F) + fl);
        float nm = __int_as_float(e.y);
        ax = fmaf(nm, v.x, ax);
        ay = fmaf(nm, v.y, ay);
    }

    // combine the two half-warp partial sums (same feature pair at lane^16)
    ax += __shfl_xor_sync(0xffffffffu, ax, 16);
    ay += __shfl_xor_sync(0xffffffffu, ay, 16);
    if (half == 0)
        ((float2*)(dst + w * F))[fl] = make_float2(ax, ay);
}

// 32-wide matvec accumulate: acc[o] += row[i] * ws[i*32+o]
__device__ __forceinline__ void mv32(const float* __restrict__ row,
                                     const float* __restrict__ ws,
                                     float acc[32]) {
    const float4* r4 = reinterpret_cast<const float4*>(row);
#pragma unroll 2
    for (int c = 0; c < 8; c++) {
        float4 v = __ldg(&r4[c]);
        float vv[4] = {v.x, v.y, v.z, v.w};
#pragma unroll
        for (int j = 0; j < 4; j++) {
            const float4* w4 = reinterpret_cast<const float4*>(&ws[(c * 4 + j) * 32]);
#pragma unroll
            for (int ob = 0; ob < 8; ob++) {
                float4 wv = w4[ob];
                acc[ob * 4 + 0] = fmaf(vv[j], wv.x, acc[ob * 4 + 0]);
                acc[ob * 4 + 1] = fmaf(vv[j], wv.y, acc[ob * 4 + 1]);
                acc[ob * 4 + 2] = fmaf(vv[j], wv.z, acc[ob * 4 + 2]);
                acc[ob * 4 + 3] = fmaf(vv[j], wv.w, acc[ob * 4 + 3]);
            }
        }
    }
}

// node-per-thread Chebyshev combine + per-graph max pool.
__global__ void __launch_bounds__(256) k_combine(
    const float* __restrict__ x,
    const int* __restrict__ batch,
    const float* __restrict__ Wc,
    const float* __restrict__ bc,
    int n)
{
    __shared__ float ws[96 * 32];   // rows 0-31: W0-W2, 32-63: W1, 64-95: 2*W2
    __shared__ float bs[32];
    int t = threadIdx.x;

    for (int l = t; l < 1024; l += 256) {
        int i = l >> 5, o = l & 31;
        float w0 = __ldg(&Wc[i * 32 + o]);
        float w1 = __ldg(&Wc[1024 + i * 32 + o]);
        float w2 = __ldg(&Wc[2048 + i * 32 + o]);
        ws[i * 32 + o] = w0 - w2;
        ws[(32 + i) * 32 + o] = w1;
        ws[(64 + i) * 32 + o] = 2.f * w2;
    }
    if (t < 32) bs[t] = __ldg(&bc[t]);
    __syncthreads();

    int nidx = blockIdx.x * 256 + t;
    int lane = t & 31;
    bool valid = nidx < n;

    float acc[32];
#pragma unroll
    for (int o = 0; o < 32; o++) acc[o] = bs[o];

    if (valid) {
        mv32(x + (long long)nidx * 32, ws, acc);
        mv32(d_t1 + (long long)nidx * 32, ws + 32 * 32, acc);
        mv32(d_p2 + (long long)nidx * 32, ws + 64 * 32, acc);
    }

    int g = valid ? batch[nidx] : -1;
    unsigned vm = __ballot_sync(0xffffffffu, valid);
    int gfirst = __shfl_sync(0xffffffffu, g, 0);
    int glast  = __shfl_sync(0xffffffffu, g, 31);

    if (vm == 0xffffffffu && gfirst == glast) {
        float myv = 0.f;
#pragma unroll
        for (int o = 0; o < 32; o++) {
            float r = acc[o];
#pragma unroll
            for (int off = 16; off; off >>= 1)
                r = fmaxf(r, __shfl_xor_sync(0xffffffffu, r, off));
            if (lane == o) myv = r;
        }
        atomicMax(&d_pool[gfirst * F + lane], fenc(myv));
    } else if (valid) {
#pragma unroll
        for (int o = 0; o < 32; o++)
            atomicMax(&d_pool[g * F + o], fenc(acc[o]));
    }
}

__global__ void k_mlp1(const float* __restrict__ W1, const float* __restrict__ b1) {
    int t = blockIdx.x * blockDim.x + threadIdx.x;
    int b = t >> 10;
    int o = t & 1023;
    float acc = __ldg(&b1[o]);
#pragma unroll
    for (int i = 0; i < 32; i++) {
        float g = fdec(d_pool[b * 32 + i]);
        acc = fmaf(g, __ldg(&W1[i * 1024 + o]), acc);
    }
    d_h1[t] = fmaxf(acc, 0.f);
}

__global__ void k_mlp2(const float* __restrict__ W2, const float* __restrict__ b2) {
    __shared__ float h1s[64 * 129];
    __shared__ float w2s[128 * 8];
    int t = threadIdx.x;
    int o0 = blockIdx.x * 8;
    int b = t >> 2;
    int jo = t & 3;
    float a0 = 0.f, a1 = 0.f;

    for (int kt = 0; kt < 1024; kt += 128) {
        for (int l = t; l < 64 * 128; l += 256) {
            int r = l >> 7, c = l & 127;
            h1s[r * 129 + c] = d_h1[r * 1024 + kt + c];
        }
        for (int l = t; l < 1024; l += 256) {
            int k = l >> 3, j = l & 7;
            w2s[l] = __ldg(&W2[(kt + k) * 512 + o0 + j]);
        }
        __syncthreads();
#pragma unroll
        for (int k = 0; k < 128; k++) {
            float h = h1s[b * 129 + k];
            a0 = fmaf(h, w2s[k * 8 + jo], a0);
            a1 = fmaf(h, w2s[k * 8 + jo + 4], a1);
        }
        __syncthreads();
    }
    d_h2[b * 512 + o0 + jo]     = fmaxf(a0 + __ldg(&b2[o0 + jo]), 0.f);
    d_h2[b * 512 + o0 + jo + 4] = fmaxf(a1 + __ldg(&b2[o0 + jo + 4]), 0.f);
}

__global__ void k_mlp3(const float* __restrict__ W3, const float* __restrict__ b3,
                       float* __restrict__ out) {
    int w = blockIdx.x * (blockDim.x >> 5) + (threadIdx.x >> 5);
    int lane = threadIdx.x & 31;
    if (w >= 256) return;
    int b = w >> 2;
    int o = w & 3;
    float s = 0.f;
    for (int k = lane; k < 512; k += 32)
        s = fmaf(d_h2[b * 512 + k], __ldg(&W3[k * 4 + o]), s);
#pragma unroll
    for (int off = 16; off; off >>= 1)
        s += __shfl_xor_sync(0xffffffffu, s, off);
    if (lane == 0) out[b * 4 + o] = s + __ldg(&b3[o]);
}

// ---------------- launch ----------------
extern "C" void kernel_launch(void* const* d_in, const int* in_sizes, int n_in,
                              void* d_out, int out_size) {
    const float* x     = (const float*)d_in[0];
    const int*   ei    = (const int*)d_in[1];
    const int*   batch = (const int*)d_in[2];
    const float* Wc    = (const float*)d_in[3];
    const float* bc    = (const float*)d_in[4];
    const float* W1    = (const float*)d_in[5];
    const float* b1    = (const float*)d_in[6];
    const float* W2    = (const float*)d_in[7];
    const float* b2    = (const float*)d_in[8];
    const float* W3    = (const float*)d_in[9];
    const float* b3    = (const float*)d_in[10];

    int N = in_sizes[0] / F;
    int E = in_sizes[1] / 2;

    void *t1p = nullptr, *p2p = nullptr;
    cudaGetSymbolAddress(&t1p, d_t1);
    cudaGetSymbolAddress(&p2p, d_p2);

    int nblk_scan = (N + SCANB - 1) / SCANB;   // 98 for N=100000

    k_init<<<(N + 255) / 256, 256>>>(N);
    k_count<<<(E + 255) / 256, 256>>>(ei, E);
    k_scan1<<<nblk_scan, SCANB>>>(N);
    k_scan3<<<nblk_scan, SCANB>>>(N, E);
    k_scatter<<<(E + 255) / 256, 256>>>(ei, E);

    int gth_blocks = (N * 32 + 255) / 256;
    k_gather<<<gth_blocks, 256>>>(x, (float*)t1p, N);
    k_gather<<<gth_blocks, 256>>>((const float*)t1p, (float*)p2p, N);

    k_combine<<<(N + 255) / 256, 256>>>(x, batch, Wc, bc, N);

    k_mlp1<<<256, 256>>>(W1, b1);
    k_mlp2<<<64, 256>>>(W2, b2);
    k_mlp3<<<32, 256>>>(W3, b3, (float*)d_out);
}